// round 3
// baseline (speedup 1.0000x reference)
#include <cuda_runtime.h>
#include <cuda_fp16.h>
#include <cstdint>

// TitansMemoryModule — algebraically decoupled formulation:
//   retrieved = k @ W^T                       (GEMM1, output-only)
//   G1 = k^T k, G2 = v^T k  (input-only reductions; grad = (2/numel)(W G1 - G2))
//   loss = (<W G1, W> - 2<G2, W> + sum(v^2)) / numel
// inputs: k (N,64) f32 | v (N,64) f32 | W (64,64) | gate_w (3,64) | gate_b (3) | S (64,64)
// output: retrieved (N*64) | loss | new_W (4096) | new_S (4096) | gates (3)

#define TILE 128
#define PH   72            // smem pitch in halves: 144B rows, conflict-free ldmatrix
#define D    64

static constexpr int KBUF = TILE * PH;                       // 9216 halves
static constexpr int SMEM_HALVES = 3 * KBUF + D * PH;        // kb0,kb1,vb,wsh
static constexpr int SMEM_BYTES  = SMEM_HALVES * 2;          // 64512 B -> 2 CTAs/SM

__device__ float g_G1[D * D];
__device__ float g_G2[D * D];
__device__ float g_ksum[D];
__device__ float g_sv;

__device__ __forceinline__ uint32_t sh_u32(const void* p) {
    return (uint32_t)__cvta_generic_to_shared(p);
}
__device__ __forceinline__ void ldsm4(uint32_t& r0, uint32_t& r1, uint32_t& r2, uint32_t& r3, uint32_t a) {
    asm volatile("ldmatrix.sync.aligned.m8n8.x4.shared.b16 {%0,%1,%2,%3},[%4];"
                 : "=r"(r0), "=r"(r1), "=r"(r2), "=r"(r3) : "r"(a));
}
__device__ __forceinline__ void ldsm4t(uint32_t& r0, uint32_t& r1, uint32_t& r2, uint32_t& r3, uint32_t a) {
    asm volatile("ldmatrix.sync.aligned.m8n8.x4.trans.shared.b16 {%0,%1,%2,%3},[%4];"
                 : "=r"(r0), "=r"(r1), "=r"(r2), "=r"(r3) : "r"(a));
}
__device__ __forceinline__ void mma16(float* c,
                                      uint32_t a0, uint32_t a1, uint32_t a2, uint32_t a3,
                                      uint32_t b0, uint32_t b1) {
    asm volatile("mma.sync.aligned.m16n8k16.row.col.f32.f16.f16.f32 "
                 "{%0,%1,%2,%3},{%4,%5,%6,%7},{%8,%9},{%0,%1,%2,%3};"
                 : "+f"(c[0]), "+f"(c[1]), "+f"(c[2]), "+f"(c[3])
                 : "r"(a0), "r"(a1), "r"(a2), "r"(a3), "r"(b0), "r"(b1));
}

__global__ void zero_scratch_kernel() {
    int t = blockIdx.x * blockDim.x + threadIdx.x;
    if (t < D * D) { g_G1[t] = 0.0f; g_G2[t] = 0.0f; }
    if (t < D)     g_ksum[t] = 0.0f;
    if (t == 0)    g_sv = 0.0f;
}

__global__ __launch_bounds__(256, 2)
void titans_main_kernel(const float* __restrict__ kmat,
                        const float* __restrict__ vmat,
                        const float* __restrict__ W,
                        float* __restrict__ ret,
                        int N) {
    extern __shared__ __half sh[];
    __half* kb0 = sh;
    __half* kb1 = sh + KBUF;
    __half* vb  = sh + 2 * KBUF;
    __half* wsh = sh + 3 * KBUF;

    const int tid  = threadIdx.x;
    const int lane = tid & 31;
    const int warp = tid >> 5;               // 0..7
    const int lp   = lane >> 2;
    const int lq   = lane & 3;
    const int row0   = warp * 16;            // GEMM1 row stripe
    const int jbase  = (warp & 3) * 16;      // reduction output stripe
    const bool is_g1 = warp < 4;             // warps 0-3: k^T k, warps 4-7: v^T k
    const int qcol   = (tid & 15) * 4;       // staging columns

    for (int i = tid; i < D * D; i += 256)
        wsh[(i >> 6) * PH + (i & 63)] = __float2half(W[i]);

    float ks4[4] = {0.f, 0.f, 0.f, 0.f};
    float sv_local = 0.0f;
    float gacc[8][4];
#pragma unroll
    for (int n = 0; n < 8; n++)
#pragma unroll
        for (int i = 0; i < 4; i++) gacc[n][i] = 0.0f;

    const int grid   = gridDim.x;
    const int ntiles = N / TILE;

    // prologue: stage first k tile
    {
        const float4* kt = reinterpret_cast<const float4*>(kmat) + (size_t)blockIdx.x * 2048;
#pragma unroll
        for (int it = 0; it < 8; it++) {
            int i = tid + it * 256;
            int r = i >> 4;
            float4 x = __ldcs(&kt[i]);
            ks4[0] += x.x; ks4[1] += x.y; ks4[2] += x.z; ks4[3] += x.w;
            *reinterpret_cast<__half2*>(&kb0[r * PH + qcol])     = __floats2half2_rn(x.x, x.y);
            *reinterpret_cast<__half2*>(&kb0[r * PH + qcol + 2]) = __floats2half2_rn(x.z, x.w);
        }
    }

    int p = 0;
    for (int tile = blockIdx.x; tile < ntiles; tile += grid, p ^= 1) {
        const __half* ks = p ? kb1 : kb0;
        __half*       kn = p ? kb0 : kb1;

        __syncthreads();   // kb[p] staged; vb free

        // issue v loads early (consumed after GEMM1)
        const float4* vt = reinterpret_cast<const float4*>(vmat) + (size_t)tile * 2048;
        float4 v4[8];
#pragma unroll
        for (int it = 0; it < 8; it++)
            v4[it] = __ldcs(&vt[tid + it * 256]);

        // ---- GEMM1: C(16x64) = k_rows @ W^T ----
        float c1[8][4];
#pragma unroll
        for (int n = 0; n < 8; n++)
#pragma unroll
            for (int i = 0; i < 4; i++) c1[n][i] = 0.0f;

#pragma unroll
        for (int kk = 0; kk < 4; kk++) {
            const int kbs = kk * 16;
            uint32_t a0, a1, a2, a3;
            ldsm4(a0, a1, a2, a3,
                  sh_u32(&ks[(row0 + (lane & 15)) * PH + kbs + ((lane >> 4) << 3)]));
#pragma unroll
            for (int j = 0; j < 4; j++) {
                const int bt = (2 * j + (lane >> 4)) * 8 + (lane & 7);
                const int bc = kbs + ((lane >> 3) & 1) * 8;
                uint32_t b0, b1, b2, b3;
                ldsm4(b0, b1, b2, b3, sh_u32(&wsh[bt * PH + bc]));
                mma16(c1[2 * j],     a0, a1, a2, a3, b0, b1);
                mma16(c1[2 * j + 1], a0, a1, a2, a3, b2, b3);
            }
        }

        // store retrieved (streaming)
        const size_t gr0 = (size_t)(tile * TILE + row0 + lp) * D;
#pragma unroll
        for (int n = 0; n < 8; n++) {
            const int col = n * 8 + 2 * lq;
            __stcs(reinterpret_cast<float2*>(&ret[gr0 + col]),
                   make_float2(c1[n][0], c1[n][1]));
            __stcs(reinterpret_cast<float2*>(&ret[gr0 + 8 * D + col]),
                   make_float2(c1[n][2], c1[n][3]));
        }

        // convert v -> vb, accumulate sum(v^2)
#pragma unroll
        for (int it = 0; it < 8; it++) {
            int r = (tid + it * 256) >> 4;
            float4 x = v4[it];
            sv_local += x.x * x.x + x.y * x.y + x.z * x.z + x.w * x.w;
            *reinterpret_cast<__half2*>(&vb[r * PH + qcol])     = __floats2half2_rn(x.x, x.y);
            *reinterpret_cast<__half2*>(&vb[r * PH + qcol + 2]) = __floats2half2_rn(x.z, x.w);
        }

        // prefetch next k tile (latency hidden under reductions)
        const int tnext = tile + grid;
        const bool have = tnext < ntiles;
        float4 kpre[8];
        {
            const float4* kt = reinterpret_cast<const float4*>(kmat) + (size_t)tnext * 2048;
#pragma unroll
            for (int it = 0; it < 8; it++)
                kpre[it] = have ? __ldcs(&kt[tid + it * 256])
                                : make_float4(0.f, 0.f, 0.f, 0.f);
        }

        __syncthreads();   // vb staged

        // ---- reductions: gacc += A^T @ k  (A = k for warps 0-3, v for warps 4-7) ----
        const __half* asrc = is_g1 ? ks : vb;
#pragma unroll
        for (int kk = 0; kk < 8; kk++) {
            const int sb = kk * 16;
            uint32_t a0, a1, a2, a3;
            ldsm4t(a0, a1, a2, a3,
                   sh_u32(&asrc[(sb + ((lane >> 4) << 3) + (lane & 7)) * PH
                                + jbase + ((lane >> 3) & 1) * 8]));
#pragma unroll
            for (int j = 0; j < 4; j++) {
                const int srow = sb + ((lane >> 3) & 1) * 8 + (lane & 7);
                const int dcol = (2 * j + (lane >> 4)) * 8;
                uint32_t b0, b1, b2, b3;
                ldsm4t(b0, b1, b2, b3, sh_u32(&ks[srow * PH + dcol]));
                mma16(gacc[2 * j],     a0, a1, a2, a3, b0, b1);
                mma16(gacc[2 * j + 1], a0, a1, a2, a3, b2, b3);
            }
        }

        // stage prefetched k into other buffer
        if (have) {
#pragma unroll
            for (int it = 0; it < 8; it++) {
                int r = (tid + it * 256) >> 4;
                float4 x = kpre[it];
                ks4[0] += x.x; ks4[1] += x.y; ks4[2] += x.z; ks4[3] += x.w;
                *reinterpret_cast<__half2*>(&kn[r * PH + qcol])     = __floats2half2_rn(x.x, x.y);
                *reinterpret_cast<__half2*>(&kn[r * PH + qcol + 2]) = __floats2half2_rn(x.z, x.w);
            }
        }
    }

    // ---- global accumulation ----
    float* gdst = is_g1 ? g_G1 : g_G2;
#pragma unroll
    for (int n = 0; n < 8; n++) {
        const int col = n * 8 + 2 * lq;
        const int r0i = (jbase + lp) * D;
        const int r1i = (jbase + lp + 8) * D;
        atomicAdd(&gdst[r0i + col],     gacc[n][0]);
        atomicAdd(&gdst[r0i + col + 1], gacc[n][1]);
        atomicAdd(&gdst[r1i + col],     gacc[n][2]);
        atomicAdd(&gdst[r1i + col + 1], gacc[n][3]);
    }
#pragma unroll
    for (int c = 0; c < 4; c++)
        atomicAdd(&g_ksum[qcol + c], ks4[c]);

    __syncthreads();
    float* red = reinterpret_cast<float*>(sh);
    red[tid] = sv_local;
    __syncthreads();
#pragma unroll
    for (int s = 128; s > 0; s >>= 1) {
        if (tid < s) red[tid] += red[tid + s];
        __syncthreads();
    }
    if (tid == 0) atomicAdd(&g_sv, red[0]);
}

__global__ void titans_final_kernel(const float* __restrict__ W,
                                    const float* __restrict__ gate_w,
                                    const float* __restrict__ gate_b,
                                    const float* __restrict__ S,
                                    float* __restrict__ out,
                                    int N) {
    __shared__ float Wsh[D * D];
    __shared__ float G1sh[D * D];
    __shared__ float gates_sh[3];
    __shared__ float red[256];
    __shared__ float red2[256];
    __shared__ float scale_sh;
    const int tid = threadIdx.x;
    const float numel = (float)N * (float)D;

    const size_t loss_off = (size_t)N * D;
    const size_t nw_off   = loss_off + 1;
    const size_t ns_off   = nw_off + D * D;
    const size_t g_off    = ns_off + D * D;

    for (int i = tid; i < D * D; i += 256) {
        Wsh[i]  = W[i];
        G1sh[i] = g_G1[i];
    }
    if (tid == 0) {
        float invN = 1.0f / (float)N;
        for (int i = 0; i < 3; i++) {
            float s = gate_b[i];
            for (int d = 0; d < D; d++) s += gate_w[i * D + d] * (g_ksum[d] * invN);
            gates_sh[i] = 1.0f / (1.0f + __expf(-s));
        }
    }
    __syncthreads();
    const float alpha = gates_sh[0];
    const float eta   = gates_sh[1];
    const float theta = gates_sh[2];

    // WG1 = W @ G1 ; dots for loss
    float wg1[16];
    float dWW = 0.0f, dG2W = 0.0f;
#pragma unroll
    for (int i = 0; i < 16; i++) {
        int idx = tid * 16 + i;
        int j = idx >> 6, dp = idx & 63;
        float acc = 0.0f;
#pragma unroll 8
        for (int d = 0; d < D; d++)
            acc += Wsh[j * D + d] * G1sh[d * D + dp];
        wg1[i] = acc;
        dWW  += acc * Wsh[idx];
        dG2W += g_G2[idx] * Wsh[idx];
    }

    // new_S / new_W
    float wlocal[16];
    float ss = 0.0f;
#pragma unroll
    for (int i = 0; i < 16; i++) {
        int idx = tid * 16 + i;
        float g = (wg1[i] - g_G2[idx]) * (2.0f / numel);
        g = fminf(1.0f, fmaxf(-1.0f, g));
        float ns = eta * S[idx] - 0.01f * theta * g;
        float nw = (1.0f - alpha) * Wsh[idx] + ns;
        out[ns_off + idx] = ns;
        wlocal[i] = nw;
        ss += nw * nw;
    }

    red[tid]  = ss;
    red2[tid] = dWW - 2.0f * dG2W;
    __syncthreads();
#pragma unroll
    for (int s = 128; s > 0; s >>= 1) {
        if (tid < s) { red[tid] += red[tid + s]; red2[tid] += red2[tid + s]; }
        __syncthreads();
    }
    if (tid == 0) {
        float wnorm = sqrtf(red[0]);
        scale_sh = (wnorm > 10.0f) ? (10.0f / (wnorm + 1e-8f)) : 1.0f;
        out[loss_off] = (g_sv + red2[0]) / numel;
    }
    __syncthreads();
    const float sc = scale_sh;
#pragma unroll
    for (int i = 0; i < 16; i++) {
        int idx = tid * 16 + i;
        out[nw_off + idx] = wlocal[i] * sc;
    }
    if (tid < 3) out[g_off + tid] = gates_sh[tid];
}

extern "C" void kernel_launch(void* const* d_in, const int* in_sizes, int n_in,
                              void* d_out, int out_size) {
    const float* k  = (const float*)d_in[0];
    const float* v  = (const float*)d_in[1];
    const float* W  = (const float*)d_in[2];
    const float* gw = (const float*)d_in[3];
    const float* gb = (const float*)d_in[4];
    const float* S  = (const float*)d_in[5];
    float* out = (float*)d_out;

    const int N = in_sizes[0] / D;

    cudaFuncSetAttribute(titans_main_kernel,
                         cudaFuncAttributeMaxDynamicSharedMemorySize, SMEM_BYTES);

    zero_scratch_kernel<<<16, 256>>>();
    titans_main_kernel<<<296, 256, SMEM_BYTES>>>(k, v, W, out, N);
    titans_final_kernel<<<1, 256>>>(W, gw, gb, S, out, N);
}

// round 4
// speedup vs baseline: 1.2177x; 1.2177x over previous
#include <cuda_runtime.h>
#include <cuda_fp16.h>
#include <cstdint>

// TitansMemoryModule — warp-specialized producer/consumer with mbarrier ring.
//   retrieved = k @ W^T ; G1 = k^T k ; G2 = v^T k
//   grad = (2/numel)(W G1 - G2) ; loss = (<W G1,W> - 2<G2,W> + sum v^2)/numel
// 512 thr/CTA, grid=148 (1 CTA/SM): warps 0-3 producers, 4-11 GEMM1, 12-15 reductions.

#define D     64
#define TILE  128
#define PH    72                     // smem pitch (halves): 144B rows, 16B-aligned, conflict-free
#define DEPTH 4

static constexpr int KBUF  = TILE * PH;           // 9216 halves per tile buffer
static constexpr int STAGE = 2 * KBUF;            // k + v per stage
static constexpr int SMEM_HALVES = DEPTH * STAGE + D * PH;
static constexpr int SMEM_BYTES  = SMEM_HALVES * 2;   // 156672 B

__device__ float g_G1[D * D];
__device__ float g_G2[D * D];
__device__ float g_ksum[D];
__device__ float g_sv;

__device__ __forceinline__ uint32_t sh_u32(const void* p) {
    return (uint32_t)__cvta_generic_to_shared(p);
}
__device__ __forceinline__ void ldsm4(uint32_t& r0, uint32_t& r1, uint32_t& r2, uint32_t& r3, uint32_t a) {
    asm volatile("ldmatrix.sync.aligned.m8n8.x4.shared.b16 {%0,%1,%2,%3},[%4];"
                 : "=r"(r0), "=r"(r1), "=r"(r2), "=r"(r3) : "r"(a));
}
__device__ __forceinline__ void ldsm4t(uint32_t& r0, uint32_t& r1, uint32_t& r2, uint32_t& r3, uint32_t a) {
    asm volatile("ldmatrix.sync.aligned.m8n8.x4.trans.shared.b16 {%0,%1,%2,%3},[%4];"
                 : "=r"(r0), "=r"(r1), "=r"(r2), "=r"(r3) : "r"(a));
}
__device__ __forceinline__ void mma16(float* c,
                                      uint32_t a0, uint32_t a1, uint32_t a2, uint32_t a3,
                                      uint32_t b0, uint32_t b1) {
    asm volatile("mma.sync.aligned.m16n8k16.row.col.f32.f16.f16.f32 "
                 "{%0,%1,%2,%3},{%4,%5,%6,%7},{%8,%9},{%0,%1,%2,%3};"
                 : "+f"(c[0]), "+f"(c[1]), "+f"(c[2]), "+f"(c[3])
                 : "r"(a0), "r"(a1), "r"(a2), "r"(a3), "r"(b0), "r"(b1));
}
__device__ __forceinline__ void mbar_init(uint32_t a, uint32_t cnt) {
    asm volatile("mbarrier.init.shared.b64 [%0], %1;" :: "r"(a), "r"(cnt) : "memory");
}
__device__ __forceinline__ void mbar_arrive(uint32_t a) {
    asm volatile("mbarrier.arrive.shared.b64 _, [%0];" :: "r"(a) : "memory");
}
__device__ __forceinline__ void mbar_wait(uint32_t a, uint32_t parity) {
    asm volatile(
        "{\n\t.reg .pred P;\n"
        "WL_%=:\n\t"
        "mbarrier.try_wait.parity.acquire.cta.shared::cta.b64 P, [%0], %1, 0x989680;\n\t"
        "@P bra WD_%=;\n\t"
        "bra WL_%=;\n"
        "WD_%=:\n\t}"
        :: "r"(a), "r"(parity) : "memory");
}

__global__ void zero_scratch_kernel() {
    int t = blockIdx.x * blockDim.x + threadIdx.x;
    if (t < D * D) { g_G1[t] = 0.0f; g_G2[t] = 0.0f; }
    if (t < D)     g_ksum[t] = 0.0f;
    if (t == 0)    g_sv = 0.0f;
}

__global__ __launch_bounds__(512, 1)
void titans_main_kernel(const float* __restrict__ kmat,
                        const float* __restrict__ vmat,
                        const float* __restrict__ W,
                        float* __restrict__ ret,
                        int N) {
    extern __shared__ __half sh[];
    __shared__ uint64_t mbar[2 * DEPTH];   // [0..3] full, [4..7] empty
    __half* wsh = sh + DEPTH * STAGE;

    const int tid  = threadIdx.x;
    const int lane = tid & 31;
    const int warp = tid >> 5;

    if (tid == 0) {
#pragma unroll
        for (int s = 0; s < DEPTH; s++) {
            mbar_init(sh_u32(&mbar[s]), 128);          // full: 128 producer threads
            mbar_init(sh_u32(&mbar[DEPTH + s]), 12);   // empty: 12 consumer warps
        }
    }
    // stage W (fp16) once
    for (int i = tid; i < D * D; i += 512)
        wsh[(i >> 6) * PH + (i & 63)] = __float2half(W[i]);
    __syncthreads();

    const int grid   = gridDim.x;
    const int ntiles = N / TILE;

    if (warp < 4) {
        // ================= PRODUCERS (128 threads) =================
        const int pt   = tid;                 // 0..127
        const int qcol = (pt & 15) * 4;
        const int rbase = pt >> 4;            // 0..7
        float ks4[4] = {0.f, 0.f, 0.f, 0.f};
        float sv = 0.0f;

        int stage = 0, phase = 1;
        for (int tile = blockIdx.x; tile < ntiles; tile += grid) {
            mbar_wait(sh_u32(&mbar[DEPTH + stage]), phase);
            __half* kb = sh + stage * STAGE;
            __half* vb = kb + KBUF;

            const float4* kt = reinterpret_cast<const float4*>(kmat) + (size_t)tile * 2048;
            const float4* vt = reinterpret_cast<const float4*>(vmat) + (size_t)tile * 2048;

            float4 a[8], b[8];
#pragma unroll
            for (int j = 0; j < 8; j++) a[j] = __ldcs(&kt[pt + j * 128]);
#pragma unroll
            for (int j = 0; j < 8; j++) b[j] = __ldcs(&kt[pt + (j + 8) * 128]);
#pragma unroll
            for (int j = 0; j < 8; j++) {
                float4 x = a[j];
                int r = rbase + j * 8;
                ks4[0] += x.x; ks4[1] += x.y; ks4[2] += x.z; ks4[3] += x.w;
                __half2 h01 = __floats2half2_rn(x.x, x.y);
                __half2 h23 = __floats2half2_rn(x.z, x.w);
                *reinterpret_cast<uint2*>(&kb[r * PH + qcol]) =
                    make_uint2(*reinterpret_cast<uint32_t*>(&h01), *reinterpret_cast<uint32_t*>(&h23));
            }
#pragma unroll
            for (int j = 0; j < 8; j++) {
                float4 x = b[j];
                int r = rbase + (j + 8) * 8;
                ks4[0] += x.x; ks4[1] += x.y; ks4[2] += x.z; ks4[3] += x.w;
                __half2 h01 = __floats2half2_rn(x.x, x.y);
                __half2 h23 = __floats2half2_rn(x.z, x.w);
                *reinterpret_cast<uint2*>(&kb[r * PH + qcol]) =
                    make_uint2(*reinterpret_cast<uint32_t*>(&h01), *reinterpret_cast<uint32_t*>(&h23));
            }
#pragma unroll
            for (int j = 0; j < 8; j++) a[j] = __ldcs(&vt[pt + j * 128]);
#pragma unroll
            for (int j = 0; j < 8; j++) b[j] = __ldcs(&vt[pt + (j + 8) * 128]);
#pragma unroll
            for (int j = 0; j < 8; j++) {
                float4 x = a[j];
                int r = rbase + j * 8;
                sv += x.x * x.x + x.y * x.y + x.z * x.z + x.w * x.w;
                __half2 h01 = __floats2half2_rn(x.x, x.y);
                __half2 h23 = __floats2half2_rn(x.z, x.w);
                *reinterpret_cast<uint2*>(&vb[r * PH + qcol]) =
                    make_uint2(*reinterpret_cast<uint32_t*>(&h01), *reinterpret_cast<uint32_t*>(&h23));
            }
#pragma unroll
            for (int j = 0; j < 8; j++) {
                float4 x = b[j];
                int r = rbase + (j + 8) * 8;
                sv += x.x * x.x + x.y * x.y + x.z * x.z + x.w * x.w;
                __half2 h01 = __floats2half2_rn(x.x, x.y);
                __half2 h23 = __floats2half2_rn(x.z, x.w);
                *reinterpret_cast<uint2*>(&vb[r * PH + qcol]) =
                    make_uint2(*reinterpret_cast<uint32_t*>(&h01), *reinterpret_cast<uint32_t*>(&h23));
            }
            mbar_arrive(sh_u32(&mbar[stage]));
            stage++; if (stage == DEPTH) { stage = 0; phase ^= 1; }
        }
        // epilogue: column sums + sum(v^2)
#pragma unroll
        for (int c = 0; c < 4; c++) atomicAdd(&g_ksum[qcol + c], ks4[c]);
#pragma unroll
        for (int off = 16; off > 0; off >>= 1)
            sv += __shfl_xor_sync(0xFFFFFFFF, sv, off);
        if (lane == 0) atomicAdd(&g_sv, sv);

    } else if (warp < 12) {
        // ================= GEMM1 warps (8): retrieved = k @ W^T =================
        const int widx = warp - 4;
        const int row0 = widx * 16;
        const int lp = lane >> 2, lq = lane & 3;

        // hoist W fragments (constant across tiles)
        uint32_t wr[4][4][4];
#pragma unroll
        for (int kk = 0; kk < 4; kk++)
#pragma unroll
            for (int j = 0; j < 4; j++) {
                const int bt = (2 * j + (lane >> 4)) * 8 + (lane & 7);
                const int bc = kk * 16 + ((lane >> 3) & 1) * 8;
                ldsm4(wr[kk][j][0], wr[kk][j][1], wr[kk][j][2], wr[kk][j][3],
                      sh_u32(&wsh[bt * PH + bc]));
            }

        int stage = 0, phase = 0;
        for (int tile = blockIdx.x; tile < ntiles; tile += grid) {
            mbar_wait(sh_u32(&mbar[stage]), phase);
            const __half* kb = sh + stage * STAGE;

            uint32_t af[4][4];
#pragma unroll
            for (int kk = 0; kk < 4; kk++)
                ldsm4(af[kk][0], af[kk][1], af[kk][2], af[kk][3],
                      sh_u32(&kb[(row0 + (lane & 15)) * PH + kk * 16 + ((lane >> 4) << 3)]));
            if (lane == 0) mbar_arrive(sh_u32(&mbar[DEPTH + stage]));   // done with smem

            float c1[8][4];
#pragma unroll
            for (int n = 0; n < 8; n++)
#pragma unroll
                for (int i = 0; i < 4; i++) c1[n][i] = 0.0f;
#pragma unroll
            for (int kk = 0; kk < 4; kk++)
#pragma unroll
                for (int j = 0; j < 4; j++) {
                    mma16(c1[2 * j],     af[kk][0], af[kk][1], af[kk][2], af[kk][3],
                          wr[kk][j][0], wr[kk][j][1]);
                    mma16(c1[2 * j + 1], af[kk][0], af[kk][1], af[kk][2], af[kk][3],
                          wr[kk][j][2], wr[kk][j][3]);
                }

            const size_t gr0 = (size_t)(tile * TILE + row0 + lp) * D;
#pragma unroll
            for (int n = 0; n < 8; n++) {
                const int col = n * 8 + 2 * lq;
                *reinterpret_cast<float2*>(&ret[gr0 + col])         = make_float2(c1[n][0], c1[n][1]);
                *reinterpret_cast<float2*>(&ret[gr0 + 8 * D + col]) = make_float2(c1[n][2], c1[n][3]);
            }
            stage++; if (stage == DEPTH) { stage = 0; phase ^= 1; }
        }

    } else {
        // ================= Reduction warps (4): G1 = k^T k, G2 = v^T k =================
        const int ridx = warp - 12;
        const int jstripe = (ridx & 1) * 32;
        const bool useV = (ridx >> 1) != 0;           // 0,1 -> G1 ; 2,3 -> G2
        const int lp = lane >> 2, lq = lane & 3;

        float gacc[2][8][4];
#pragma unroll
        for (int mi = 0; mi < 2; mi++)
#pragma unroll
            for (int n = 0; n < 8; n++)
#pragma unroll
                for (int i = 0; i < 4; i++) gacc[mi][n][i] = 0.0f;

        int stage = 0, phase = 0;
        for (int tile = blockIdx.x; tile < ntiles; tile += grid) {
            mbar_wait(sh_u32(&mbar[stage]), phase);
            const __half* kb = sh + stage * STAGE;
            const __half* asrc = useV ? (kb + KBUF) : kb;

#pragma unroll
            for (int kk = 0; kk < 8; kk++) {
                const int sb = kk * 16;
                uint32_t am[2][4];
#pragma unroll
                for (int mi = 0; mi < 2; mi++) {
                    const int jcol = jstripe + mi * 16;
                    ldsm4t(am[mi][0], am[mi][1], am[mi][2], am[mi][3],
                           sh_u32(&asrc[(sb + ((lane >> 4) << 3) + (lane & 7)) * PH
                                        + jcol + ((lane >> 3) & 1) * 8]));
                }
                const int srow = sb + ((lane >> 3) & 1) * 8 + (lane & 7);
#pragma unroll
                for (int jn = 0; jn < 4; jn++) {
                    const int dcol = (2 * jn + (lane >> 4)) * 8;
                    uint32_t b0, b1, b2, b3;
                    ldsm4t(b0, b1, b2, b3, sh_u32(&kb[srow * PH + dcol]));
#pragma unroll
                    for (int mi = 0; mi < 2; mi++) {
                        mma16(gacc[mi][2 * jn],     am[mi][0], am[mi][1], am[mi][2], am[mi][3], b0, b1);
                        mma16(gacc[mi][2 * jn + 1], am[mi][0], am[mi][1], am[mi][2], am[mi][3], b2, b3);
                    }
                }
            }
            if (lane == 0) mbar_arrive(sh_u32(&mbar[DEPTH + stage]));
            stage++; if (stage == DEPTH) { stage = 0; phase ^= 1; }
        }

        float* gdst = useV ? g_G2 : g_G1;
#pragma unroll
        for (int mi = 0; mi < 2; mi++)
#pragma unroll
            for (int n = 0; n < 8; n++) {
                const int col = n * 8 + 2 * lq;
                const int r0i = (jstripe + mi * 16 + lp) * D;
                const int r1i = (jstripe + mi * 16 + lp + 8) * D;
                atomicAdd(&gdst[r0i + col],     gacc[mi][n][0]);
                atomicAdd(&gdst[r0i + col + 1], gacc[mi][n][1]);
                atomicAdd(&gdst[r1i + col],     gacc[mi][n][2]);
                atomicAdd(&gdst[r1i + col + 1], gacc[mi][n][3]);
            }
    }
}

__global__ void titans_final_kernel(const float* __restrict__ W,
                                    const float* __restrict__ gate_w,
                                    const float* __restrict__ gate_b,
                                    const float* __restrict__ S,
                                    float* __restrict__ out,
                                    int N) {
    __shared__ float Wsh[D * D];
    __shared__ float G1sh[D * D];
    __shared__ float gates_sh[3];
    __shared__ float red[256];
    __shared__ float red2[256];
    __shared__ float scale_sh;
    const int tid = threadIdx.x;
    const float numel = (float)N * (float)D;

    const size_t loss_off = (size_t)N * D;
    const size_t nw_off   = loss_off + 1;
    const size_t ns_off   = nw_off + D * D;
    const size_t g_off    = ns_off + D * D;

    for (int i = tid; i < D * D; i += 256) {
        Wsh[i]  = W[i];
        G1sh[i] = g_G1[i];
    }
    if (tid == 0) {
        float invN = 1.0f / (float)N;
        for (int i = 0; i < 3; i++) {
            float s = gate_b[i];
            for (int d = 0; d < D; d++) s += gate_w[i * D + d] * (g_ksum[d] * invN);
            gates_sh[i] = 1.0f / (1.0f + __expf(-s));
        }
    }
    __syncthreads();
    const float alpha = gates_sh[0];
    const float eta   = gates_sh[1];
    const float theta = gates_sh[2];

    float wg1[16];
    float dWW = 0.0f, dG2W = 0.0f;
#pragma unroll
    for (int i = 0; i < 16; i++) {
        int idx = tid * 16 + i;
        int j = idx >> 6, dp = idx & 63;
        float acc = 0.0f;
#pragma unroll 8
        for (int d = 0; d < D; d++)
            acc += Wsh[j * D + d] * G1sh[d * D + dp];
        wg1[i] = acc;
        dWW  += acc * Wsh[idx];
        dG2W += g_G2[idx] * Wsh[idx];
    }

    float wlocal[16];
    float ss = 0.0f;
#pragma unroll
    for (int i = 0; i < 16; i++) {
        int idx = tid * 16 + i;
        float g = (wg1[i] - g_G2[idx]) * (2.0f / numel);
        g = fminf(1.0f, fmaxf(-1.0f, g));
        float ns = eta * S[idx] - 0.01f * theta * g;
        float nw = (1.0f - alpha) * Wsh[idx] + ns;
        out[ns_off + idx] = ns;
        wlocal[i] = nw;
        ss += nw * nw;
    }

    red[tid]  = ss;
    red2[tid] = dWW - 2.0f * dG2W;
    __syncthreads();
#pragma unroll
    for (int s = 128; s > 0; s >>= 1) {
        if (tid < s) { red[tid] += red[tid + s]; red2[tid] += red2[tid + s]; }
        __syncthreads();
    }
    if (tid == 0) {
        float wnorm = sqrtf(red[0]);
        scale_sh = (wnorm > 10.0f) ? (10.0f / (wnorm + 1e-8f)) : 1.0f;
        out[loss_off] = (g_sv + red2[0]) / numel;
    }
    __syncthreads();
    const float sc = scale_sh;
#pragma unroll
    for (int i = 0; i < 16; i++) {
        int idx = tid * 16 + i;
        out[nw_off + idx] = wlocal[i] * sc;
    }
    if (tid < 3) out[g_off + tid] = gates_sh[tid];
}

extern "C" void kernel_launch(void* const* d_in, const int* in_sizes, int n_in,
                              void* d_out, int out_size) {
    const float* k  = (const float*)d_in[0];
    const float* v  = (const float*)d_in[1];
    const float* W  = (const float*)d_in[2];
    const float* gw = (const float*)d_in[3];
    const float* gb = (const float*)d_in[4];
    const float* S  = (const float*)d_in[5];
    float* out = (float*)d_out;

    const int N = in_sizes[0] / D;

    cudaFuncSetAttribute(titans_main_kernel,
                         cudaFuncAttributeMaxDynamicSharedMemorySize, SMEM_BYTES);

    zero_scratch_kernel<<<16, 256>>>();
    titans_main_kernel<<<148, 512, SMEM_BYTES>>>(k, v, W, out, N);
    titans_final_kernel<<<1, 256>>>(W, gw, gb, S, out, N);
}